// round 12
// baseline (speedup 1.0000x reference)
#include <cuda_runtime.h>
#include <cuda_bf16.h>
#include <cuda_fp16.h>
#include <cstdint>
#include <cstddef>

// out[8192,4096] = x[8192,4096] @ quantize(W)^T * scale + bias
#define MROWS 8192
#define KDIM  4096
#define NDIM  4096

constexpr int BM = 128, BN = 128, BK = 64;
constexpr int NST = 3;
constexpr int KTILES = KDIM / BK;                 // 64
constexpr int TILE_A = BM * BK * 2;               // 16KB
constexpr int TILE_B = BN * BK * 2;               // 16KB
constexpr int STAGE_BYTES = TILE_A + TILE_B;      // 32KB
constexpr int OFF_A = 0;
constexpr int OFF_B = TILE_A;
constexpr int SMEM_TOTAL = NST * STAGE_BYTES;     // 96KB -> 2 CTAs/SM

// ---------------- static scratch (allocations forbidden) ----------------
__device__ __align__(16) __half g_XF[(size_t)MROWS * KDIM];  // 64 MB fp16 x
__device__ __align__(16) __half g_Q [(size_t)NDIM  * KDIM];  // 32 MB fp16 ternary

// ---------------- helpers (sm_80-level PTX only) ----------------
__device__ __forceinline__ uint32_t smem_u32(const void* p) {
    uint32_t a;
    asm("{ .reg .u64 t; cvta.to.shared.u64 t, %1; cvt.u32.u64 %0, t; }" : "=r"(a) : "l"(p));
    return a;
}
__device__ __forceinline__ void cp16(uint32_t dst, const void* src) {
    asm volatile("cp.async.cg.shared.global [%0], [%1], 16;" :: "r"(dst), "l"(src));
}
__device__ __forceinline__ void cp_commit() {
    asm volatile("cp.async.commit_group;" ::: "memory");
}
__device__ __forceinline__ uint32_t swz128(uint32_t off) {   // SW128, 128B rows
    return off ^ ((off >> 3) & 0x70);
}
__device__ __forceinline__ void ldm_x4(uint32_t* r, uint32_t addr) {
    asm volatile("ldmatrix.sync.aligned.m8n8.x4.shared.b16 {%0,%1,%2,%3}, [%4];"
                 : "=r"(r[0]), "=r"(r[1]), "=r"(r[2]), "=r"(r[3]) : "r"(addr));
}
__device__ __forceinline__ void mma_fp16(float* c, const uint32_t* a, const uint32_t* b) {
    asm volatile(
        "mma.sync.aligned.m16n8k16.row.col.f32.f16.f16.f32 "
        "{%0,%1,%2,%3}, {%4,%5,%6,%7}, {%8,%9}, {%0,%1,%2,%3};"
        : "+f"(c[0]), "+f"(c[1]), "+f"(c[2]), "+f"(c[3])
        : "r"(a[0]), "r"(a[1]), "r"(a[2]), "r"(a[3]), "r"(b[0]), "r"(b[1]));
}
__device__ __forceinline__ uint32_t packh2(float a, float b) {
    __half2 h = __floats2half2_rn(a, b);
    return *reinterpret_cast<uint32_t*>(&h);
}

// ---------------- kernel 1: quantize W (W row cached in smem) + convert x ----------------
__global__ __launch_bounds__(256) void prep_kernel(const float* __restrict__ W,
                                                   const float* __restrict__ x) {
    const int tid = threadIdx.x;
    if (blockIdx.x < NDIM) {
        __shared__ float4 wrow[KDIM / 4];      // 16KB
        __shared__ float red[8];
        __shared__ float alphaS;
        const int row = blockIdx.x;
        const float4* w4 = reinterpret_cast<const float4*>(W + (size_t)row * KDIM);
        float s = 0.f;
        #pragma unroll 4
        for (int i = tid; i < KDIM / 4; i += 256) {
            float4 v = w4[i];
            wrow[i] = v;
            s += fabsf(v.x) + fabsf(v.y) + fabsf(v.z) + fabsf(v.w);
        }
        #pragma unroll
        for (int o = 16; o > 0; o >>= 1) s += __shfl_xor_sync(0xFFFFFFFFu, s, o);
        if ((tid & 31) == 0) red[tid >> 5] = s;
        __syncthreads();
        if (tid == 0) {
            float t = 0.f;
            #pragma unroll
            for (int i = 0; i < 8; i++) t += red[i];
            alphaS = t / (float)KDIM;
        }
        __syncthreads();
        const float alpha = alphaS;
        uint2* q2 = reinterpret_cast<uint2*>(g_Q + (size_t)row * KDIM);
        #pragma unroll 4
        for (int i = tid; i < KDIM / 4; i += 256) {
            float4 v = wrow[i];
            float q0 = (v.x > alpha) ? 1.f : ((v.x < -alpha) ? -1.f : 0.f);
            float q1 = (v.y > alpha) ? 1.f : ((v.y < -alpha) ? -1.f : 0.f);
            float q2v = (v.z > alpha) ? 1.f : ((v.z < -alpha) ? -1.f : 0.f);
            float q3 = (v.w > alpha) ? 1.f : ((v.w < -alpha) ? -1.f : 0.f);
            uint2 o; o.x = packh2(q0, q1); o.y = packh2(q2v, q3);
            q2[i] = o;
        }
    } else {
        const size_t n4 = (size_t)MROWS * KDIM / 4;
        const float4* x4 = reinterpret_cast<const float4*>(x);
        uint2* h4 = reinterpret_cast<uint2*>(g_XF);
        const size_t stride = (size_t)(gridDim.x - NDIM) * 256;
        for (size_t i = (size_t)(blockIdx.x - NDIM) * 256 + tid; i < n4; i += stride) {
            float4 v = x4[i];
            uint2 hh; hh.x = packh2(v.x, v.y); hh.y = packh2(v.z, v.w);
            h4[i] = hh;
        }
    }
}

#define ROWB ((size_t)KDIM * 2)

// ---------------- kernel 2: 2 CTA/SM, mid-stage sync, cross-stage frag prefetch ----------------
__global__ __launch_bounds__(256, 2) void gemm_kernel(const float* __restrict__ scale,
                                                      const float* __restrict__ bias,
                                                      float* __restrict__ out) {
    extern __shared__ __align__(1024) char smem[];
    const uint32_t sb = smem_u32(smem);
    const int tid = threadIdx.x;
    const int wid = tid >> 5;
    const int lid = tid & 31;
    const int ntile = blockIdx.x;   // 32
    const int mtile = blockIdx.y;   // 64

    const int warp_m = wid & 3;     // 4 warps along M: 32 rows each
    const int warp_n = wid >> 2;    // 2 warps along N: 64 cols each

    // ---- per-thread copy mapping: 1024 chunks each for A/B, 4 per thread ----
    const int r0 = tid >> 3;            // base row (0..31), +32 per chunk
    const int ch = tid & 7;
    const uint32_t dOff = swz128((uint32_t)(r0 * 128 + ch * 16));   // row%8 invariant +32
    const char* aCp = reinterpret_cast<const char*>(g_XF) +
                      (size_t)(mtile * BM + r0) * ROWB + (size_t)ch * 16;
    const char* bCp = reinterpret_cast<const char*>(g_Q) +
                      (size_t)(ntile * BN + r0) * ROWB + (size_t)ch * 16;

    float acc[2][8][4];
    #pragma unroll
    for (int mi = 0; mi < 2; mi++)
        #pragma unroll
        for (int ni = 0; ni < 8; ni++)
            #pragma unroll
            for (int k = 0; k < 4; k++) acc[mi][ni][k] = 0.f;

    // ---- prologue: stages 0,1 in flight ----
    #pragma unroll
    for (int s = 0; s < 2; s++) {
        const uint32_t stg = sb + (uint32_t)s * STAGE_BYTES;
        #pragma unroll
        for (int i = 0; i < 4; i++)
            cp16(stg + OFF_A + dOff + (uint32_t)(i * 4096),
                 aCp + (size_t)s * 128 + (size_t)i * 32 * ROWB);
        #pragma unroll
        for (int i = 0; i < 4; i++)
            cp16(stg + OFF_B + dOff + (uint32_t)(i * 4096),
                 bCp + (size_t)s * 128 + (size_t)i * 32 * ROWB);
        cp_commit();
    }
    aCp += 256; bCp += 256;   // next stage to issue = kt+2

    // ldmatrix lane address components
    const int lane15 = lid & 15;
    const int laneHiA = lid >> 4;
    const int rowBl = (lid & 7) + ((lid >> 4) & 1) * 8;
    const int chBl  = (lid >> 3) & 1;
    const uint32_t aAddrBase = (uint32_t)((warp_m * 32 + lane15) * 128 + laneHiA * 16);
    const uint32_t bAddrBase = (uint32_t)((warp_n * 64 + rowBl) * 128 + chBl * 16);

    uint32_t af[2][2][4];   // [buf][m16][regs]
    uint32_t bf[2][4][4];   // [buf][n16 quad][regs]

    // wait for stage 0, make visible, prefetch its k16=0 fragments
    asm volatile("cp.async.wait_group 1;" ::: "memory");
    __syncthreads();
    #pragma unroll
    for (int mi = 0; mi < 2; mi++)
        ldm_x4(af[0][mi], sb + OFF_A + swz128(aAddrBase + (uint32_t)(mi * 16 * 128)));
    #pragma unroll
    for (int nq = 0; nq < 4; nq++)
        ldm_x4(bf[0][nq], sb + OFF_B + swz128(bAddrBase + (uint32_t)(nq * 16 * 128)));

    int sIdx = 0;
    for (int kt = 0; kt < KTILES; kt++) {
        const uint32_t stage = sb + (uint32_t)sIdx * STAGE_BYTES;
        const uint32_t aS = stage + OFF_A;
        const uint32_t bS = stage + OFF_B;

        #pragma unroll
        for (int k16 = 0; k16 < 4; k16++) {
            const int cur = k16 & 1;
            const int nxt = cur ^ 1;

            if (k16 == 2) {
                // mid-stage: kt+1 data arrival + visibility; buffer (kt+2)%3 free for refill
                asm volatile("cp.async.wait_group 0;" ::: "memory");
                __syncthreads();
                if (kt + 2 < KTILES) {
                    int sj = sIdx + 2; if (sj >= NST) sj -= NST;
                    const uint32_t stg = sb + (uint32_t)sj * STAGE_BYTES;
                    #pragma unroll
                    for (int i = 0; i < 4; i++)
                        cp16(stg + OFF_A + dOff + (uint32_t)(i * 4096),
                             aCp + (size_t)i * 32 * ROWB);
                    #pragma unroll
                    for (int i = 0; i < 4; i++)
                        cp16(stg + OFF_B + dOff + (uint32_t)(i * 4096),
                             bCp + (size_t)i * 32 * ROWB);
                    aCp += 128; bCp += 128;
                    cp_commit();
                }
            }

            if (k16 < 3) {
                // prefetch next k16 of current stage
                const uint32_t kOff = (uint32_t)((k16 + 1) * 32);
                #pragma unroll
                for (int mi = 0; mi < 2; mi++)
                    ldm_x4(af[nxt][mi],
                           aS + swz128(aAddrBase + kOff + (uint32_t)(mi * 16 * 128)));
                #pragma unroll
                for (int nq = 0; nq < 4; nq++)
                    ldm_x4(bf[nxt][nq],
                           bS + swz128(bAddrBase + kOff + (uint32_t)(nq * 16 * 128)));
            } else if (kt + 1 < KTILES) {
                // cross-stage prefetch: next stage's k16=0 (safe after mid-stage barrier)
                int sn = sIdx + 1; if (sn >= NST) sn -= NST;
                const uint32_t nstg = sb + (uint32_t)sn * STAGE_BYTES;
                #pragma unroll
                for (int mi = 0; mi < 2; mi++)
                    ldm_x4(af[nxt][mi],
                           nstg + OFF_A + swz128(aAddrBase + (uint32_t)(mi * 16 * 128)));
                #pragma unroll
                for (int nq = 0; nq < 4; nq++)
                    ldm_x4(bf[nxt][nq],
                           nstg + OFF_B + swz128(bAddrBase + (uint32_t)(nq * 16 * 128)));
            }

            #pragma unroll
            for (int mi = 0; mi < 2; mi++)
                #pragma unroll
                for (int ni = 0; ni < 8; ni++)
                    mma_fp16(acc[mi][ni], af[cur][mi], &bf[cur][ni >> 1][(ni & 1) * 2]);
        }

        if (++sIdx == NST) sIdx = 0;
    }

    // epilogue: scale/bias via L2-hot __ldg + direct float2 stores
    const int qrow = lid >> 2;
    const int qcol = (lid & 3) * 2;
    #pragma unroll
    for (int mi = 0; mi < 2; mi++) {
        #pragma unroll
        for (int ni = 0; ni < 8; ni++) {
            const int gcol = ntile * BN + warp_n * 64 + ni * 8 + qcol;
            const float2 sc = __ldg(reinterpret_cast<const float2*>(scale + gcol));
            const float2 bi = __ldg(reinterpret_cast<const float2*>(bias + gcol));
            const int grow0 = mtile * BM + warp_m * 32 + mi * 16 + qrow;
            float2 v0, v1;
            v0.x = acc[mi][ni][0] * sc.x + bi.x;
            v0.y = acc[mi][ni][1] * sc.y + bi.y;
            v1.x = acc[mi][ni][2] * sc.x + bi.x;
            v1.y = acc[mi][ni][3] * sc.y + bi.y;
            *reinterpret_cast<float2*>(out + (size_t)grow0 * NDIM + gcol) = v0;
            *reinterpret_cast<float2*>(out + (size_t)(grow0 + 8) * NDIM + gcol) = v1;
        }
    }
}

// ---------------- launch ----------------
extern "C" void kernel_launch(void* const* d_in, const int* in_sizes, int n_in,
                              void* d_out, int out_size) {
    const float* x      = (const float*)d_in[0];
    const float* weight = (const float*)d_in[1];
    const float* scale  = (const float*)d_in[2];
    const float* bias   = (const float*)d_in[3];
    float* out = (float*)d_out;

    prep_kernel<<<NDIM + 8192, 256>>>(weight, x);

    cudaFuncSetAttribute(gemm_kernel, cudaFuncAttributeMaxDynamicSharedMemorySize, SMEM_TOTAL);
    dim3 grid(NDIM / BN, MROWS / BM);   // 32 x 64
    gemm_kernel<<<grid, 256, SMEM_TOTAL>>>(scale, bias, out);
}

// round 13
// speedup vs baseline: 1.2355x; 1.2355x over previous
#include <cuda_runtime.h>
#include <cuda_bf16.h>
#include <cuda_fp16.h>
#include <cstdint>
#include <cstddef>

// out[8192,4096] = x[8192,4096] @ quantize(W)^T * scale + bias
#define MROWS 8192
#define KDIM  4096
#define NDIM  4096

constexpr int BM = 128, BN = 128, BK = 64;
constexpr int NST = 3;
constexpr int KTILES = KDIM / BK;                 // 64
constexpr int TILE_A = BM * BK * 2;               // 16KB
constexpr int TILE_B = BN * BK * 2;               // 16KB
constexpr int STAGE_BYTES = TILE_A + TILE_B;      // 32KB
constexpr int OFF_A = 0;
constexpr int OFF_B = TILE_A;
constexpr int SMEM_TOTAL = NST * STAGE_BYTES;     // 96KB -> 2 CTAs/SM

// ---------------- static scratch (allocations forbidden) ----------------
__device__ __align__(16) __half g_XF[(size_t)MROWS * KDIM];  // 64 MB fp16 x
__device__ __align__(16) __half g_Q [(size_t)NDIM  * KDIM];  // 32 MB fp16 ternary

// ---------------- helpers (sm_80-level PTX only) ----------------
__device__ __forceinline__ uint32_t smem_u32(const void* p) {
    uint32_t a;
    asm("{ .reg .u64 t; cvta.to.shared.u64 t, %1; cvt.u32.u64 %0, t; }" : "=r"(a) : "l"(p));
    return a;
}
__device__ __forceinline__ void cp16(uint32_t dst, const void* src) {
    asm volatile("cp.async.cg.shared.global [%0], [%1], 16;" :: "r"(dst), "l"(src));
}
__device__ __forceinline__ void cp_commit() {
    asm volatile("cp.async.commit_group;" ::: "memory");
}
__device__ __forceinline__ uint32_t swz128(uint32_t off) {   // SW128, 128B rows
    return off ^ ((off >> 3) & 0x70);
}
__device__ __forceinline__ void ldm_x4(uint32_t* r, uint32_t addr) {
    asm volatile("ldmatrix.sync.aligned.m8n8.x4.shared.b16 {%0,%1,%2,%3}, [%4];"
                 : "=r"(r[0]), "=r"(r[1]), "=r"(r[2]), "=r"(r[3]) : "r"(addr));
}
__device__ __forceinline__ void mma_fp16(float* c, const uint32_t* a, const uint32_t* b) {
    asm volatile(
        "mma.sync.aligned.m16n8k16.row.col.f32.f16.f16.f32 "
        "{%0,%1,%2,%3}, {%4,%5,%6,%7}, {%8,%9}, {%0,%1,%2,%3};"
        : "+f"(c[0]), "+f"(c[1]), "+f"(c[2]), "+f"(c[3])
        : "r"(a[0]), "r"(a[1]), "r"(a[2]), "r"(a[3]), "r"(b[0]), "r"(b[1]));
}
__device__ __forceinline__ uint32_t packh2(float a, float b) {
    __half2 h = __floats2half2_rn(a, b);
    return *reinterpret_cast<uint32_t*>(&h);
}

// ---------------- kernel 1: quantize W (W row cached in smem) + convert x ----------------
__global__ __launch_bounds__(256) void prep_kernel(const float* __restrict__ W,
                                                   const float* __restrict__ x) {
    const int tid = threadIdx.x;
    if (blockIdx.x < NDIM) {
        __shared__ float4 wrow[KDIM / 4];      // 16KB
        __shared__ float red[8];
        __shared__ float alphaS;
        const int row = blockIdx.x;
        const float4* w4 = reinterpret_cast<const float4*>(W + (size_t)row * KDIM);
        float s = 0.f;
        #pragma unroll 4
        for (int i = tid; i < KDIM / 4; i += 256) {
            float4 v = w4[i];
            wrow[i] = v;
            s += fabsf(v.x) + fabsf(v.y) + fabsf(v.z) + fabsf(v.w);
        }
        #pragma unroll
        for (int o = 16; o > 0; o >>= 1) s += __shfl_xor_sync(0xFFFFFFFFu, s, o);
        if ((tid & 31) == 0) red[tid >> 5] = s;
        __syncthreads();
        if (tid == 0) {
            float t = 0.f;
            #pragma unroll
            for (int i = 0; i < 8; i++) t += red[i];
            alphaS = t / (float)KDIM;
        }
        __syncthreads();
        const float alpha = alphaS;
        uint2* q2 = reinterpret_cast<uint2*>(g_Q + (size_t)row * KDIM);
        #pragma unroll 4
        for (int i = tid; i < KDIM / 4; i += 256) {
            float4 v = wrow[i];
            float q0 = (v.x > alpha) ? 1.f : ((v.x < -alpha) ? -1.f : 0.f);
            float q1 = (v.y > alpha) ? 1.f : ((v.y < -alpha) ? -1.f : 0.f);
            float q2v = (v.z > alpha) ? 1.f : ((v.z < -alpha) ? -1.f : 0.f);
            float q3 = (v.w > alpha) ? 1.f : ((v.w < -alpha) ? -1.f : 0.f);
            uint2 o; o.x = packh2(q0, q1); o.y = packh2(q2v, q3);
            q2[i] = o;
        }
    } else {
        const size_t n4 = (size_t)MROWS * KDIM / 4;
        const float4* x4 = reinterpret_cast<const float4*>(x);
        uint2* h4 = reinterpret_cast<uint2*>(g_XF);
        const size_t stride = (size_t)(gridDim.x - NDIM) * 256;
        for (size_t i = (size_t)(blockIdx.x - NDIM) * 256 + tid; i < n4; i += stride) {
            float4 v = x4[i];
            uint2 hh; hh.x = packh2(v.x, v.y); hh.y = packh2(v.z, v.w);
            h4[i] = hh;
        }
    }
}

#define ROWB ((size_t)KDIM * 2)

// ---------------- kernel 2: 128-thread CTA, 64x64 warp tiles, 2 CTAs/SM ----------------
__global__ __launch_bounds__(128, 2) void gemm_kernel(const float* __restrict__ scale,
                                                      const float* __restrict__ bias,
                                                      float* __restrict__ out) {
    extern __shared__ __align__(1024) char smem[];
    const uint32_t sb = smem_u32(smem);
    const int tid = threadIdx.x;
    const int wid = tid >> 5;
    const int lid = tid & 31;
    const int ntile = blockIdx.x;   // 32
    const int mtile = blockIdx.y;   // 64

    const int warp_m = wid & 1;     // 2 warps along M: 64 rows each
    const int warp_n = wid >> 1;    // 2 warps along N: 64 cols each

    // ---- per-thread copy mapping: 128 threads; A/B 8 chunks each; rows advance +16 ----
    const int r0 = tid >> 3;            // 0..15
    const int ch = tid & 7;
    const uint32_t dOff = swz128((uint32_t)(r0 * 128 + ch * 16));  // row%8 invariant +16
    const char* aCp = reinterpret_cast<const char*>(g_XF) +
                      (size_t)(mtile * BM + r0) * ROWB + (size_t)ch * 16;
    const char* bCp = reinterpret_cast<const char*>(g_Q) +
                      (size_t)(ntile * BN + r0) * ROWB + (size_t)ch * 16;

    float acc[4][8][4];
    #pragma unroll
    for (int mi = 0; mi < 4; mi++)
        #pragma unroll
        for (int ni = 0; ni < 8; ni++)
            #pragma unroll
            for (int k = 0; k < 4; k++) acc[mi][ni][k] = 0.f;

    // ---- prologue: stages 0,1 in flight ----
    #pragma unroll
    for (int s = 0; s < 2; s++) {
        const uint32_t stg = sb + (uint32_t)s * STAGE_BYTES;
        #pragma unroll
        for (int i = 0; i < 8; i++)
            cp16(stg + OFF_A + dOff + (uint32_t)(i * 2048),
                 aCp + (size_t)s * 128 + (size_t)i * 16 * ROWB);
        #pragma unroll
        for (int i = 0; i < 8; i++)
            cp16(stg + OFF_B + dOff + (uint32_t)(i * 2048),
                 bCp + (size_t)s * 128 + (size_t)i * 16 * ROWB);
        cp_commit();
    }
    aCp += 256; bCp += 256;   // next stage to issue = kt+2

    // ldmatrix lane address components
    const int lane15 = lid & 15;
    const int laneHiA = lid >> 4;
    const int rowBl = (lid & 7) + ((lid >> 4) & 1) * 8;
    const int chBl  = (lid >> 3) & 1;
    const uint32_t aAddrBase = (uint32_t)((warp_m * 64 + lane15) * 128 + laneHiA * 16);
    const uint32_t bAddrBase = (uint32_t)((warp_n * 64 + rowBl) * 128 + chBl * 16);

    uint32_t af[2][4][4];   // [buf][m16][regs]
    uint32_t bf[2][4][4];   // [buf][n16 quad][regs]

    int sIdx = 0;
    for (int kt = 0; kt < KTILES; kt++) {
        asm volatile("cp.async.wait_group 1;" ::: "memory");
        __syncthreads();

        const uint32_t stage = sb + (uint32_t)sIdx * STAGE_BYTES;
        const uint32_t aS = stage + OFF_A;
        const uint32_t bS = stage + OFF_B;

        // k16=0 fragments into buffer 0 FIRST (start latency early)
        #pragma unroll
        for (int mi = 0; mi < 4; mi++)
            ldm_x4(af[0][mi], aS + swz128(aAddrBase + (uint32_t)(mi * 16 * 128)));
        #pragma unroll
        for (int nq = 0; nq < 4; nq++)
            ldm_x4(bf[0][nq], bS + swz128(bAddrBase + (uint32_t)(nq * 16 * 128)));

        // issue stage kt+2 under the LDSM shadow
        if (kt + 2 < KTILES) {
            int sj = sIdx + 2; if (sj >= NST) sj -= NST;
            const uint32_t stg = sb + (uint32_t)sj * STAGE_BYTES;
            #pragma unroll
            for (int i = 0; i < 8; i++)
                cp16(stg + OFF_A + dOff + (uint32_t)(i * 2048), aCp + (size_t)i * 16 * ROWB);
            #pragma unroll
            for (int i = 0; i < 8; i++)
                cp16(stg + OFF_B + dOff + (uint32_t)(i * 2048), bCp + (size_t)i * 16 * ROWB);
            aCp += 128; bCp += 128;
        }
        cp_commit();

        #pragma unroll
        for (int k16 = 0; k16 < 4; k16++) {
            const int cur = k16 & 1;
            if (k16 < 3) {                    // prefetch next k16 into other buffer
                const int nxt = cur ^ 1;
                const uint32_t kOff = (uint32_t)((k16 + 1) * 32);
                #pragma unroll
                for (int mi = 0; mi < 4; mi++)
                    ldm_x4(af[nxt][mi],
                           aS + swz128(aAddrBase + kOff + (uint32_t)(mi * 16 * 128)));
                #pragma unroll
                for (int nq = 0; nq < 4; nq++)
                    ldm_x4(bf[nxt][nq],
                           bS + swz128(bAddrBase + kOff + (uint32_t)(nq * 16 * 128)));
            }
            #pragma unroll
            for (int mi = 0; mi < 4; mi++)
                #pragma unroll
                for (int ni = 0; ni < 8; ni++)
                    mma_fp16(acc[mi][ni], af[cur][mi], &bf[cur][ni >> 1][(ni & 1) * 2]);
        }

        if (++sIdx == NST) sIdx = 0;
    }

    // epilogue: scale/bias via L2-hot __ldg + direct float2 stores
    const int qrow = lid >> 2;
    const int qcol = (lid & 3) * 2;
    #pragma unroll
    for (int mi = 0; mi < 4; mi++) {
        #pragma unroll
        for (int ni = 0; ni < 8; ni++) {
            const int gcol = ntile * BN + warp_n * 64 + ni * 8 + qcol;
            const float2 sc = __ldg(reinterpret_cast<const float2*>(scale + gcol));
            const float2 bi = __ldg(reinterpret_cast<const float2*>(bias + gcol));
            const int grow0 = mtile * BM + warp_m * 64 + mi * 16 + qrow;
            float2 v0, v1;
            v0.x = acc[mi][ni][0] * sc.x + bi.x;
            v0.y = acc[mi][ni][1] * sc.y + bi.y;
            v1.x = acc[mi][ni][2] * sc.x + bi.x;
            v1.y = acc[mi][ni][3] * sc.y + bi.y;
            *reinterpret_cast<float2*>(out + (size_t)grow0 * NDIM + gcol) = v0;
            *reinterpret_cast<float2*>(out + (size_t)(grow0 + 8) * NDIM + gcol) = v1;
        }
    }
}

// ---------------- launch ----------------
extern "C" void kernel_launch(void* const* d_in, const int* in_sizes, int n_in,
                              void* d_out, int out_size) {
    const float* x      = (const float*)d_in[0];
    const float* weight = (const float*)d_in[1];
    const float* scale  = (const float*)d_in[2];
    const float* bias   = (const float*)d_in[3];
    float* out = (float*)d_out;

    prep_kernel<<<NDIM + 8192, 256>>>(weight, x);

    cudaFuncSetAttribute(gemm_kernel, cudaFuncAttributeMaxDynamicSharedMemorySize, SMEM_TOTAL);
    dim3 grid(NDIM / BN, MROWS / BM);   // 32 x 64
    gemm_kernel<<<grid, 128, SMEM_TOTAL>>>(scale, bias, out);
}

// round 14
// speedup vs baseline: 1.2476x; 1.0098x over previous
#include <cuda_runtime.h>
#include <cuda_bf16.h>
#include <cuda_fp16.h>
#include <cstdint>
#include <cstddef>

// out[8192,4096] = x[8192,4096] @ quantize(W)^T * scale + bias
#define MROWS 8192
#define KDIM  4096
#define NDIM  4096

constexpr int BM = 128, BN = 128, BK = 64;
constexpr int NST = 3;
constexpr int KTILES = KDIM / BK;                 // 64
constexpr int TILE_A = BM * BK * 2;               // 16KB
constexpr int TILE_B = BN * BK * 2;               // 16KB
constexpr int STAGE_BYTES = TILE_A + TILE_B;      // 32KB
constexpr int OFF_A = 0;
constexpr int OFF_B = TILE_A;
constexpr int SMEM_TOTAL = NST * STAGE_BYTES;     // 96KB -> 2 CTAs/SM

// ---------------- static scratch (allocations forbidden) ----------------
__device__ __align__(16) __half g_XF[(size_t)MROWS * KDIM];  // 64 MB fp16 x
__device__ __align__(16) __half g_Q [(size_t)NDIM  * KDIM];  // 32 MB fp16 ternary

// ---------------- helpers (sm_80-level PTX only) ----------------
__device__ __forceinline__ uint32_t smem_u32(const void* p) {
    uint32_t a;
    asm("{ .reg .u64 t; cvta.to.shared.u64 t, %1; cvt.u32.u64 %0, t; }" : "=r"(a) : "l"(p));
    return a;
}
__device__ __forceinline__ void cp16(uint32_t dst, const void* src) {
    asm volatile("cp.async.cg.shared.global [%0], [%1], 16;" :: "r"(dst), "l"(src));
}
__device__ __forceinline__ void cp_commit() {
    asm volatile("cp.async.commit_group;" ::: "memory");
}
__device__ __forceinline__ uint32_t swz128(uint32_t off) {   // SW128, 128B rows
    return off ^ ((off >> 3) & 0x70);
}
__device__ __forceinline__ void ldm_x4(uint32_t* r, uint32_t addr) {
    asm volatile("ldmatrix.sync.aligned.m8n8.x4.shared.b16 {%0,%1,%2,%3}, [%4];"
                 : "=r"(r[0]), "=r"(r[1]), "=r"(r[2]), "=r"(r[3]) : "r"(addr));
}
__device__ __forceinline__ void mma_fp16(float* c, const uint32_t* a, const uint32_t* b) {
    asm volatile(
        "mma.sync.aligned.m16n8k16.row.col.f32.f16.f16.f32 "
        "{%0,%1,%2,%3}, {%4,%5,%6,%7}, {%8,%9}, {%0,%1,%2,%3};"
        : "+f"(c[0]), "+f"(c[1]), "+f"(c[2]), "+f"(c[3])
        : "r"(a[0]), "r"(a[1]), "r"(a[2]), "r"(a[3]), "r"(b[0]), "r"(b[1]));
}
__device__ __forceinline__ uint32_t packh2(float a, float b) {
    __half2 h = __floats2half2_rn(a, b);
    return *reinterpret_cast<uint32_t*>(&h);
}

// ---------------- kernel 1: quantize W (W row cached in smem) + convert x ----------------
__global__ __launch_bounds__(256) void prep_kernel(const float* __restrict__ W,
                                                   const float* __restrict__ x) {
    const int tid = threadIdx.x;
    if (blockIdx.x < NDIM) {
        __shared__ float4 wrow[KDIM / 4];      // 16KB
        __shared__ float red[8];
        __shared__ float alphaS;
        const int row = blockIdx.x;
        const float4* w4 = reinterpret_cast<const float4*>(W + (size_t)row * KDIM);
        float s = 0.f;
        #pragma unroll 4
        for (int i = tid; i < KDIM / 4; i += 256) {
            float4 v = w4[i];
            wrow[i] = v;
            s += fabsf(v.x) + fabsf(v.y) + fabsf(v.z) + fabsf(v.w);
        }
        #pragma unroll
        for (int o = 16; o > 0; o >>= 1) s += __shfl_xor_sync(0xFFFFFFFFu, s, o);
        if ((tid & 31) == 0) red[tid >> 5] = s;
        __syncthreads();
        if (tid == 0) {
            float t = 0.f;
            #pragma unroll
            for (int i = 0; i < 8; i++) t += red[i];
            alphaS = t / (float)KDIM;
        }
        __syncthreads();
        const float alpha = alphaS;
        uint2* q2 = reinterpret_cast<uint2*>(g_Q + (size_t)row * KDIM);
        #pragma unroll 4
        for (int i = tid; i < KDIM / 4; i += 256) {
            float4 v = wrow[i];
            float q0 = (v.x > alpha) ? 1.f : ((v.x < -alpha) ? -1.f : 0.f);
            float q1 = (v.y > alpha) ? 1.f : ((v.y < -alpha) ? -1.f : 0.f);
            float q2v = (v.z > alpha) ? 1.f : ((v.z < -alpha) ? -1.f : 0.f);
            float q3 = (v.w > alpha) ? 1.f : ((v.w < -alpha) ? -1.f : 0.f);
            uint2 o; o.x = packh2(q0, q1); o.y = packh2(q2v, q3);
            q2[i] = o;
        }
    } else {
        const size_t n4 = (size_t)MROWS * KDIM / 4;
        const float4* x4 = reinterpret_cast<const float4*>(x);
        uint2* h4 = reinterpret_cast<uint2*>(g_XF);
        const size_t stride = (size_t)(gridDim.x - NDIM) * 256;
        for (size_t i = (size_t)(blockIdx.x - NDIM) * 256 + tid; i < n4; i += stride) {
            float4 v = x4[i];
            uint2 hh; hh.x = packh2(v.x, v.y); hh.y = packh2(v.z, v.w);
            h4[i] = hh;
        }
    }
}

#define ROWB ((size_t)KDIM * 2)

// ---------------- kernel 2: 128-thread CTA, 64x64 warp tiles, tail-handoff pipeline ----------------
__global__ __launch_bounds__(128, 2) void gemm_kernel(const float* __restrict__ scale,
                                                      const float* __restrict__ bias,
                                                      float* __restrict__ out) {
    extern __shared__ __align__(1024) char smem[];
    const uint32_t sb = smem_u32(smem);
    const int tid = threadIdx.x;
    const int wid = tid >> 5;
    const int lid = tid & 31;
    const int ntile = blockIdx.x;   // 32
    const int mtile = blockIdx.y;   // 64

    const int warp_m = wid & 1;     // 2 warps along M: 64 rows each
    const int warp_n = wid >> 1;    // 2 warps along N: 64 cols each

    // ---- per-thread copy mapping: 128 threads; A/B 8 chunks each; rows advance +16 ----
    const int r0 = tid >> 3;            // 0..15
    const int ch = tid & 7;
    const uint32_t dOff = swz128((uint32_t)(r0 * 128 + ch * 16));  // row%8 invariant +16
    const char* aCp = reinterpret_cast<const char*>(g_XF) +
                      (size_t)(mtile * BM + r0) * ROWB + (size_t)ch * 16;
    const char* bCp = reinterpret_cast<const char*>(g_Q) +
                      (size_t)(ntile * BN + r0) * ROWB + (size_t)ch * 16;

    float acc[4][8][4];
    #pragma unroll
    for (int mi = 0; mi < 4; mi++)
        #pragma unroll
        for (int ni = 0; ni < 8; ni++)
            #pragma unroll
            for (int k = 0; k < 4; k++) acc[mi][ni][k] = 0.f;

    // ---- prologue: stages 0,1 in flight ----
    #pragma unroll
    for (int s = 0; s < 2; s++) {
        const uint32_t stg = sb + (uint32_t)s * STAGE_BYTES;
        #pragma unroll
        for (int i = 0; i < 8; i++)
            cp16(stg + OFF_A + dOff + (uint32_t)(i * 2048),
                 aCp + (size_t)s * 128 + (size_t)i * 16 * ROWB);
        #pragma unroll
        for (int i = 0; i < 8; i++)
            cp16(stg + OFF_B + dOff + (uint32_t)(i * 2048),
                 bCp + (size_t)s * 128 + (size_t)i * 16 * ROWB);
        cp_commit();
    }
    aCp += 256; bCp += 256;   // next stage to issue = kt+2

    // ldmatrix lane address components
    const int lane15 = lid & 15;
    const int laneHiA = lid >> 4;
    const int rowBl = (lid & 7) + ((lid >> 4) & 1) * 8;
    const int chBl  = (lid >> 3) & 1;
    const uint32_t aAddrBase = (uint32_t)((warp_m * 64 + lane15) * 128 + laneHiA * 16);
    const uint32_t bAddrBase = (uint32_t)((warp_n * 64 + rowBl) * 128 + chBl * 16);

    uint32_t af[2][4][4];   // [buf][m16][regs]
    uint32_t bf[2][4][4];   // [buf][n16 quad][regs]

    // wait for stage 0 (pending {0,1} -> <=1 means 0 done), visibility, prefetch its k0
    asm volatile("cp.async.wait_group 1;" ::: "memory");
    __syncthreads();
    #pragma unroll
    for (int mi = 0; mi < 4; mi++)
        ldm_x4(af[0][mi], sb + OFF_A + swz128(aAddrBase + (uint32_t)(mi * 16 * 128)));
    #pragma unroll
    for (int nq = 0; nq < 4; nq++)
        ldm_x4(bf[0][nq], sb + OFF_B + swz128(bAddrBase + (uint32_t)(nq * 16 * 128)));

    int sIdx = 0;
    for (int kt = 0; kt < KTILES; kt++) {
        const uint32_t stage = sb + (uint32_t)sIdx * STAGE_BYTES;
        const uint32_t aS = stage + OFF_A;
        const uint32_t bS = stage + OFF_B;

        #pragma unroll
        for (int k16 = 0; k16 < 4; k16++) {
            const int cur = k16 & 1;
            const int nxt = cur ^ 1;

            if (k16 < 3) {
                // prefetch next k16 of current stage
                const uint32_t kOff = (uint32_t)((k16 + 1) * 32);
                #pragma unroll
                for (int mi = 0; mi < 4; mi++)
                    ldm_x4(af[nxt][mi],
                           aS + swz128(aAddrBase + kOff + (uint32_t)(mi * 16 * 128)));
                #pragma unroll
                for (int nq = 0; nq < 4; nq++)
                    ldm_x4(bf[nxt][nq],
                           bS + swz128(bAddrBase + kOff + (uint32_t)(nq * 16 * 128)));
            } else if (kt + 1 < KTILES) {
                // tail handoff: copies for kt+2 -> commit -> FIFO wait for kt+1 -> barrier
                // -> prefetch kt+1's k0 fragments. Buffer (sIdx+2)%3 was last read in
                // stage kt-1 (all warps past that stage's barrier) -> safe to refill.
                if (kt + 2 < KTILES) {
                    int sj = sIdx + 2; if (sj >= NST) sj -= NST;
                    const uint32_t stg = sb + (uint32_t)sj * STAGE_BYTES;
                    #pragma unroll
                    for (int i = 0; i < 8; i++)
                        cp16(stg + OFF_A + dOff + (uint32_t)(i * 2048),
                             aCp + (size_t)i * 16 * ROWB);
                    #pragma unroll
                    for (int i = 0; i < 8; i++)
                        cp16(stg + OFF_B + dOff + (uint32_t)(i * 2048),
                             bCp + (size_t)i * 16 * ROWB);
                    aCp += 128; bCp += 128;
                }
                cp_commit();
                asm volatile("cp.async.wait_group 1;" ::: "memory");
                __syncthreads();
                int sn = sIdx + 1; if (sn >= NST) sn -= NST;
                const uint32_t nstg = sb + (uint32_t)sn * STAGE_BYTES;
                #pragma unroll
                for (int mi = 0; mi < 4; mi++)
                    ldm_x4(af[nxt][mi],
                           nstg + OFF_A + swz128(aAddrBase + (uint32_t)(mi * 16 * 128)));
                #pragma unroll
                for (int nq = 0; nq < 4; nq++)
                    ldm_x4(bf[nxt][nq],
                           nstg + OFF_B + swz128(bAddrBase + (uint32_t)(nq * 16 * 128)));
            }

            #pragma unroll
            for (int mi = 0; mi < 4; mi++)
                #pragma unroll
                for (int ni = 0; ni < 8; ni++)
                    mma_fp16(acc[mi][ni], af[cur][mi], &bf[cur][ni >> 1][(ni & 1) * 2]);
        }

        if (++sIdx == NST) sIdx = 0;
    }

    // epilogue: scale/bias via L2-hot __ldg + direct float2 stores
    const int qrow = lid >> 2;
    const int qcol = (lid & 3) * 2;
    #pragma unroll
    for (int mi = 0; mi < 4; mi++) {
        #pragma unroll
        for (int ni = 0; ni < 8; ni++) {
            const int gcol = ntile * BN + warp_n * 64 + ni * 8 + qcol;
            const float2 sc = __ldg(reinterpret_cast<const float2*>(scale + gcol));
            const float2 bi = __ldg(reinterpret_cast<const float2*>(bias + gcol));
            const int grow0 = mtile * BM + warp_m * 64 + mi * 16 + qrow;
            float2 v0, v1;
            v0.x = acc[mi][ni][0] * sc.x + bi.x;
            v0.y = acc[mi][ni][1] * sc.y + bi.y;
            v1.x = acc[mi][ni][2] * sc.x + bi.x;
            v1.y = acc[mi][ni][3] * sc.y + bi.y;
            *reinterpret_cast<float2*>(out + (size_t)grow0 * NDIM + gcol) = v0;
            *reinterpret_cast<float2*>(out + (size_t)(grow0 + 8) * NDIM + gcol) = v1;
        }
    }
}

// ---------------- launch ----------------
extern "C" void kernel_launch(void* const* d_in, const int* in_sizes, int n_in,
                              void* d_out, int out_size) {
    const float* x      = (const float*)d_in[0];
    const float* weight = (const float*)d_in[1];
    const float* scale  = (const float*)d_in[2];
    const float* bias   = (const float*)d_in[3];
    float* out = (float*)d_out;

    prep_kernel<<<NDIM + 8192, 256>>>(weight, x);

    cudaFuncSetAttribute(gemm_kernel, cudaFuncAttributeMaxDynamicSharedMemorySize, SMEM_TOTAL);
    dim3 grid(NDIM / BN, MROWS / BM);   // 32 x 64
    gemm_kernel<<<grid, 128, SMEM_TOTAL>>>(scale, bias, out);
}